// round 8
// baseline (speedup 1.0000x reference)
#include <cuda_runtime.h>
#include <cuda_bf16.h>
#include <stdint.h>

// Problem constants
#define B_ 8
#define N_ 512
#define D_ 768
#define A_ 12
#define E_ 64
#define M_ (B_ * N_)   // 4096

// ---------------------------------------------------------------------------
// PTX helpers (all baseline features: valid for compute_103 virtual arch)
// ---------------------------------------------------------------------------
__device__ __forceinline__ uint32_t smem_u32(const void* p) {
    uint32_t a;
    asm("{ .reg .u64 t; cvta.to.shared.u64 t, %1; cvt.u32.u64 %0, t; }" : "=r"(a) : "l"(p));
    return a;
}
__device__ __forceinline__ void ldsm_x4(uint32_t* r, uint32_t addr) {
    asm volatile("ldmatrix.sync.aligned.m8n8.x4.shared.b16 {%0,%1,%2,%3}, [%4];"
        : "=r"(r[0]), "=r"(r[1]), "=r"(r[2]), "=r"(r[3]) : "r"(addr));
}
#define CP16(dst, src) asm volatile("cp.async.cg.shared.global [%0], [%1], 16;" :: "r"(dst), "l"(src))
#define CP_COMMIT() asm volatile("cp.async.commit_group;" ::: "memory")
#define CP_WAIT1() asm volatile("cp.async.wait_group 1;" ::: "memory")
#define CP_WAIT0() asm volatile("cp.async.wait_group 0;" ::: "memory")

__device__ __forceinline__ void mma16816(float* c,
        uint32_t a0, uint32_t a1, uint32_t a2, uint32_t a3,
        uint32_t b0, uint32_t b1) {
    asm volatile(
        "mma.sync.aligned.m16n8k16.row.col.f32.bf16.bf16.f32 "
        "{%0,%1,%2,%3}, {%4,%5,%6,%7}, {%8,%9}, {%0,%1,%2,%3};"
        : "+f"(c[0]), "+f"(c[1]), "+f"(c[2]), "+f"(c[3])
        : "r"(a0), "r"(a1), "r"(a2), "r"(a3), "r"(b0), "r"(b1));
}

// ---------------------------------------------------------------------------
// Scratch (device globals: allocation-free)
// ---------------------------------------------------------------------------
__device__ float g_h[B_ * A_ * N_ * E_];     // [b][a][i][e]
__device__ float g_src[B_ * A_ * N_];
__device__ float g_dst[B_ * A_ * N_];
__device__ float g_att[B_ * N_ * D_];        // [b][i][a*64+e]
__device__ int   g_adj_int;
// bf16 split operands (hi + lo)
__device__ __align__(16) __nv_bfloat16 g_fh[M_ * D_];
__device__ __align__(16) __nv_bfloat16 g_fl[M_ * D_];
__device__ __align__(16) __nv_bfloat16 g_w1h[D_ * D_];  // W^T: row n=a*64+e, col k=d
__device__ __align__(16) __nv_bfloat16 g_w1l[D_ * D_];
__device__ __align__(16) __nv_bfloat16 g_w2h[D_ * D_];  // Hw: row n, col k=d
__device__ __align__(16) __nv_bfloat16 g_w2l[D_ * D_];

// ---------------------------------------------------------------------------
// adj dtype detection
// ---------------------------------------------------------------------------
__global__ void detect_adj_kernel(const int* __restrict__ adj) {
    int ok = 1;
    for (int v = threadIdx.x; v < 1024; v += 32) {
        int w = adj[v];
        if (w != 0 && w != 1) ok = 0;
    }
#pragma unroll
    for (int o = 16; o; o >>= 1) ok &= __shfl_xor_sync(0xffffffffu, ok, o);
    if (threadIdx.x == 0) g_adj_int = ok;
}

// ---------------------------------------------------------------------------
// fp32 -> bf16 hi/lo split conversions
// ---------------------------------------------------------------------------
__device__ __forceinline__ void split2(float x, __nv_bfloat16& h, __nv_bfloat16& l) {
    h = __float2bfloat16(x);
    l = __float2bfloat16(x - __bfloat162float(h));
}

__global__ void conv_feat_kernel(const float* __restrict__ f) {
    const int g4 = (blockIdx.x * 256 + threadIdx.x) * 4;
    float4 v = *(const float4*)(f + g4);
    __nv_bfloat16 h0, h1, h2, h3, l0, l1, l2, l3;
    split2(v.x, h0, l0); split2(v.y, h1, l1); split2(v.z, h2, l2); split2(v.w, h3, l3);
    ((__nv_bfloat162*)(g_fh + g4))[0] = __nv_bfloat162(h0, h1);
    ((__nv_bfloat162*)(g_fh + g4))[1] = __nv_bfloat162(h2, h3);
    ((__nv_bfloat162*)(g_fl + g4))[0] = __nv_bfloat162(l0, l1);
    ((__nv_bfloat162*)(g_fl + g4))[1] = __nv_bfloat162(l2, l3);
}

__global__ void conv_w1_kernel(const float* __restrict__ W) {
    const int n = blockIdx.x;
    const int a = n >> 6, e = n & 63;
    for (int d = threadIdx.x; d < D_; d += 256) {
        float x = W[(a * D_ + d) * E_ + e];
        __nv_bfloat16 h, l;
        split2(x, h, l);
        g_w1h[n * D_ + d] = h;
        g_w1l[n * D_ + d] = l;
    }
}

__global__ void conv_w2_kernel(const float* __restrict__ Hw) {
    const int g4 = (blockIdx.x * 256 + threadIdx.x) * 4;
    float4 v = *(const float4*)(Hw + g4);
    __nv_bfloat16 h0, h1, h2, h3, l0, l1, l2, l3;
    split2(v.x, h0, l0); split2(v.y, h1, l1); split2(v.z, h2, l2); split2(v.w, h3, l3);
    ((__nv_bfloat162*)(g_w2h + g4))[0] = __nv_bfloat162(h0, h1);
    ((__nv_bfloat162*)(g_w2h + g4))[1] = __nv_bfloat162(h2, h3);
    ((__nv_bfloat162*)(g_w2l + g4))[0] = __nv_bfloat162(l0, l1);
    ((__nv_bfloat162*)(g_w2l + g4))[1] = __nv_bfloat162(l2, l3);
}

// ---------------------------------------------------------------------------
// HMMA bf16x3 GEMM: 128x128 block, 8 warps (4m x 2n), warp 32x64.
// K chunks of 32; cp.async double buffer; ldmatrix fragment loads.
// ---------------------------------------------------------------------------
#define KC_ 32
#define NKC_ (D_ / KC_)          // 24
#define TROW_B 80                // bytes per smem tile row (32 bf16 + 8 pad)
#define TILE_B (128 * TROW_B)    // 10240
#define BUF_B (4 * TILE_B)       // 40960 (Ah,Al,Bh,Bl)
#define GEMM_SMEM (2 * BUF_B)    // 81920

__device__ __forceinline__ void hmma_mainloop(
        float acc[2][8][4],
        const __nv_bfloat16* __restrict__ Ah, const __nv_bfloat16* __restrict__ Al,
        const __nv_bfloat16* __restrict__ Bh, const __nv_bfloat16* __restrict__ Bl,
        int m0, int n0, char* sm) {
    const int tid = threadIdx.x;
    const int warp = tid >> 5, lane = tid & 31;
    const int wm = warp & 3, wn = warp >> 2;

    const int lr = tid >> 1;
    const int lce = (tid & 1) * 16;
    const uint32_t sto = (uint32_t)lr * TROW_B + (tid & 1) * 32;
    const uint32_t smu = smem_u32(sm);

    const __nv_bfloat16* pAh = Ah + (size_t)(m0 + lr) * D_ + lce;
    const __nv_bfloat16* pAl = Al + (size_t)(m0 + lr) * D_ + lce;
    const __nv_bfloat16* pBh = Bh + (size_t)(n0 + lr) * D_ + lce;
    const __nv_bfloat16* pBl = Bl + (size_t)(n0 + lr) * D_ + lce;

#define ISSUE(kc, buf) do {                                                  \
    uint32_t _bb = smu + (buf) * BUF_B + sto;                                \
    const int _o = (kc) * KC_;                                               \
    CP16(_bb, pAh + _o);                 CP16(_bb + 16, pAh + _o + 8);       \
    CP16(_bb + TILE_B, pAl + _o);        CP16(_bb + TILE_B + 16, pAl + _o + 8); \
    CP16(_bb + 2 * TILE_B, pBh + _o);    CP16(_bb + 2 * TILE_B + 16, pBh + _o + 8); \
    CP16(_bb + 3 * TILE_B, pBl + _o);    CP16(_bb + 3 * TILE_B + 16, pBl + _o + 8); \
    CP_COMMIT(); } while (0)

    ISSUE(0, 0);

    // ldmatrix address components
    const int arow = (lane & 7) + ((lane >> 3) & 1) * 8;
    const int acolb = (lane >> 4) * 16;
    const int brow = (lane & 7) + (lane >> 4) * 8;
    const int bcolb = ((lane >> 3) & 1) * 16;

    for (int kc = 0; kc < NKC_; ++kc) {
        if (kc + 1 < NKC_) { ISSUE(kc + 1, (kc + 1) & 1); CP_WAIT1(); }
        else               { CP_WAIT0(); }
        __syncthreads();
        const uint32_t bufb = smu + (kc & 1) * BUF_B;
        const uint32_t aA0 = bufb + (uint32_t)(wm * 32 + arow) * TROW_B + acolb;
        const uint32_t bB0 = bufb + 2 * TILE_B + (uint32_t)(wn * 64 + brow) * TROW_B + bcolb;
#pragma unroll
        for (int ks = 0; ks < 2; ++ks) {
            uint32_t ah[2][4], al[2][4], bh[4][4], bl[4][4];
#pragma unroll
            for (int mf = 0; mf < 2; ++mf) {
                ldsm_x4(ah[mf], aA0 + mf * 16 * TROW_B + ks * 32);
                ldsm_x4(al[mf], aA0 + TILE_B + mf * 16 * TROW_B + ks * 32);
            }
#pragma unroll
            for (int nfp = 0; nfp < 4; ++nfp) {
                ldsm_x4(bh[nfp], bB0 + nfp * 16 * TROW_B + ks * 32);
                ldsm_x4(bl[nfp], bB0 + TILE_B + nfp * 16 * TROW_B + ks * 32);
            }
#pragma unroll
            for (int nfp = 0; nfp < 4; ++nfp)
#pragma unroll
                for (int hf = 0; hf < 2; ++hf) {
                    const int nf = nfp * 2 + hf;
                    const uint32_t b0h = bh[nfp][hf * 2], b1h = bh[nfp][hf * 2 + 1];
                    const uint32_t b0l = bl[nfp][hf * 2], b1l = bl[nfp][hf * 2 + 1];
#pragma unroll
                    for (int mf = 0; mf < 2; ++mf) {
                        mma16816(acc[mf][nf], ah[mf][0], ah[mf][1], ah[mf][2], ah[mf][3], b0h, b1h);
                        mma16816(acc[mf][nf], al[mf][0], al[mf][1], al[mf][2], al[mf][3], b0h, b1h);
                        mma16816(acc[mf][nf], ah[mf][0], ah[mf][1], ah[mf][2], ah[mf][3], b0l, b1l);
                    }
                }
        }
        __syncthreads();
    }
#undef ISSUE
}

// ---------------------------------------------------------------------------
// GEMM-1 (HMMA): h = feat @ W^T -> g_h[b][a][i][e]
// ---------------------------------------------------------------------------
__global__ __launch_bounds__(256) void gemm1_tc_kernel() {
    extern __shared__ char sm[];
    const int m0 = blockIdx.y << 7;
    const int n0 = blockIdx.x << 7;
    float acc[2][8][4];
#pragma unroll
    for (int mf = 0; mf < 2; ++mf)
#pragma unroll
        for (int nf = 0; nf < 8; ++nf)
#pragma unroll
            for (int q = 0; q < 4; ++q) acc[mf][nf][q] = 0.f;

    hmma_mainloop(acc, g_fh, g_fl, g_w1h, g_w1l, m0, n0, sm);

    const int warp = threadIdx.x >> 5, lane = threadIdx.x & 31;
    const int wm = warp & 3, wn = warp >> 2;
    const int g = lane >> 2, t = lane & 3;
#pragma unroll
    for (int mf = 0; mf < 2; ++mf)
#pragma unroll
        for (int nf = 0; nf < 8; ++nf) {
            const int m = m0 + wm * 32 + mf * 16 + g;
            const int n = n0 + wn * 64 + nf * 8 + 2 * t;
            const int b = m >> 9, i = m & (N_ - 1);
            const int a = n >> 6, e = n & 63;
            float* p0 = &g_h[(((b * A_) + a) * N_ + i) * E_ + e];
            float* p1 = &g_h[(((b * A_) + a) * N_ + (i + 8)) * E_ + e];
            *(float2*)p0 = make_float2(acc[mf][nf][0], acc[mf][nf][1]);
            *(float2*)p1 = make_float2(acc[mf][nf][2], acc[mf][nf][3]);
        }
}

// ---------------------------------------------------------------------------
// GEMM-2 (HMMA) + fused epilogue:
// gate = sigmoid(feat @ Hw^T + Hb); out = gate*elu(g_att) + (1-gate)*feat
// ---------------------------------------------------------------------------
__device__ __forceinline__ float blend_one(float accv, float hb, float att, float f) {
    float gt = 1.f / (1.f + __expf(-(accv + hb)));
    float fo = att > 0.f ? att : (__expf(att) - 1.f);
    return gt * fo + (1.f - gt) * f;
}

__global__ __launch_bounds__(256) void gemm2_tc_kernel(const float* __restrict__ feat,
                                                       const float* __restrict__ Hb,
                                                       float* __restrict__ out) {
    extern __shared__ char sm[];
    const int m0 = blockIdx.y << 7;
    const int n0 = blockIdx.x << 7;
    float acc[2][8][4];
#pragma unroll
    for (int mf = 0; mf < 2; ++mf)
#pragma unroll
        for (int nf = 0; nf < 8; ++nf)
#pragma unroll
            for (int q = 0; q < 4; ++q) acc[mf][nf][q] = 0.f;

    hmma_mainloop(acc, g_fh, g_fl, g_w2h, g_w2l, m0, n0, sm);

    const int warp = threadIdx.x >> 5, lane = threadIdx.x & 31;
    const int wm = warp & 3, wn = warp >> 2;
    const int g = lane >> 2, t = lane & 3;
#pragma unroll
    for (int mf = 0; mf < 2; ++mf)
#pragma unroll
        for (int nf = 0; nf < 8; ++nf) {
            const int m = m0 + wm * 32 + mf * 16 + g;
            const int n = n0 + wn * 64 + nf * 8 + 2 * t;
            float2 hb = *(const float2*)(Hb + n);
#pragma unroll
            for (int rr = 0; rr < 2; ++rr) {
                const int mm = m + rr * 8;
                float2 av = *(const float2*)(g_att + (size_t)mm * D_ + n);
                float2 fv = *(const float2*)(feat + (size_t)mm * D_ + n);
                float2 ov;
                ov.x = blend_one(acc[mf][nf][rr * 2 + 0], hb.x, av.x, fv.x);
                ov.y = blend_one(acc[mf][nf][rr * 2 + 1], hb.y, av.y, fv.y);
                *(float2*)(out + (size_t)mm * D_ + n) = ov;
            }
        }
}

// ---------------------------------------------------------------------------
// src/dst: warp per (b,a,i) row: tanh(h) . w_src / w_dst
// ---------------------------------------------------------------------------
__global__ void srcdst_kernel(const float* __restrict__ wsrc, const float* __restrict__ wdst) {
    const int warp = (blockIdx.x * blockDim.x + threadIdx.x) >> 5;
    const int lane = threadIdx.x & 31;
    const int a = (warp >> 9) % A_;
    const float* hr = g_h + (size_t)warp * E_;
    float t0 = tanhf(hr[lane]);
    float t1 = tanhf(hr[lane + 32]);
    float s = t0 * __ldg(wsrc + a * E_ + lane) + t1 * __ldg(wsrc + a * E_ + lane + 32);
    float d = t0 * __ldg(wdst + a * E_ + lane) + t1 * __ldg(wdst + a * E_ + lane + 32);
#pragma unroll
    for (int o = 16; o; o >>= 1) {
        s += __shfl_xor_sync(0xffffffffu, s, o);
        d += __shfl_xor_sync(0xffffffffu, d, o);
    }
    if (lane == 0) { g_src[warp] = s; g_dst[warp] = d; }
}

// ---------------------------------------------------------------------------
// Attention (HMMA): block = (itile of 128, a, b), 8 warps.
// Phase A: h[b,a] -> transposed bf16 hi/lo HT[e][j] in smem.
// Phase B: warp-per-row softmax stats (max, 1/sum) + packed mask bits.
// Phase C: 8 chunks of 64 j: recompute P -> bf16 hi/lo tile, then
//          HMMA  Ph@Hh + Pl@Hh + Ph@Hl  (fp32 accum).
// ---------------------------------------------------------------------------
#define HT_ROWB 1040             // 512 bf16 + 8 pad
#define P_ROWB 144               // 64 bf16 + 8 pad
#define OFF_HTH 0
#define OFF_HTL 66560
#define OFF_PBH 133120
#define OFF_PBL 151552
#define OFF_SRC 169984
#define OFF_DST 170496
#define OFF_RMX 172544
#define OFF_RIV 173056
#define OFF_MS  173568
#define ATT_SMEM_B (OFF_MS + 8192)   // 181760

__global__ __launch_bounds__(256) void attn_kernel(const void* __restrict__ adjv,
                                                   const float* __restrict__ bbias) {
    extern __shared__ char sm[];
    const uint32_t smu = smem_u32(sm);
    char* HTh = sm + OFF_HTH;
    char* HTl = sm + OFF_HTL;
    char* Pbh = sm + OFF_PBH;
    char* Pbl = sm + OFF_PBL;
    float* s_src = (float*)(sm + OFF_SRC);
    float* s_dst = (float*)(sm + OFF_DST);
    float* s_rmax = (float*)(sm + OFF_RMX);
    float* s_rinv = (float*)(sm + OFF_RIV);
    unsigned short* Ms = (unsigned short*)(sm + OFF_MS);   // [32 jwords][128 rows]

    const int tid = threadIdx.x;
    const int lane = tid & 31, warp = tid >> 5;
    const int b = blockIdx.z, a = blockIdx.y, it = blockIdx.x;
    const int ba = b * A_ + a;
    const int i0 = it * 128;

    // ---- Phase A: transpose + split h into HT; load vectors ----
    {
        const float4* hsrc = (const float4*)(g_h + (size_t)ba * N_ * E_);
        for (int v = tid; v < N_ * E_ / 4; v += 256) {
            float4 x = hsrc[v];
            const int j = v >> 4;
            const int e0 = (v & 15) << 2;
#pragma unroll
            for (int q = 0; q < 4; ++q) {
                __nv_bfloat16 hh, ll;
                split2((&x.x)[q], hh, ll);
                *(__nv_bfloat16*)(HTh + (e0 + q) * HT_ROWB + j * 2) = hh;
                *(__nv_bfloat16*)(HTl + (e0 + q) * HT_ROWB + j * 2) = ll;
            }
        }
        if (tid < 128) s_src[tid] = g_src[ba * N_ + i0 + tid];
        s_dst[tid] = g_dst[ba * N_ + tid];
        s_dst[tid + 256] = g_dst[ba * N_ + tid + 256];
    }
    __syncthreads();

    // ---- Phase B: stats (warp per row), packed mask bits ----
    const int adj_int = g_adj_int;
    for (int rr = warp; rr < 128; rr += 8) {
        const size_t rowoff = (size_t)(b * N_ + i0 + rr) * N_;
        unsigned mbits = 0;
        if (adj_int) {
            const uint4* ap = (const uint4*)((const int*)adjv + rowoff + lane * 16);
#pragma unroll
            for (int q = 0; q < 4; ++q) {
                uint4 w = ap[q];
                mbits |= (w.x ? 1u : 0u) << (q * 4 + 0);
                mbits |= (w.y ? 1u : 0u) << (q * 4 + 1);
                mbits |= (w.z ? 1u : 0u) << (q * 4 + 2);
                mbits |= (w.w ? 1u : 0u) << (q * 4 + 3);
            }
        } else {
            uint4 w = *(const uint4*)((const uint8_t*)adjv + rowoff + lane * 16);
            unsigned ws[4] = {w.x, w.y, w.z, w.w};
#pragma unroll
            for (int q = 0; q < 4; ++q)
#pragma unroll
                for (int bq = 0; bq < 4; ++bq)
                    mbits |= (((ws[q] >> (8 * bq)) & 0xffu) ? 1u : 0u) << (q * 4 + bq);
        }
        const float sbase = s_src[rr];
        alignas(16) float dv[16];
#pragma unroll
        for (int c = 0; c < 4; ++c)
            *(float4*)&dv[c * 4] = *(const float4*)&s_dst[lane * 16 + c * 4];
        float l[16];
        float mx = -1e30f;
#pragma unroll
        for (int q = 0; q < 16; ++q) {
            float v = sbase + dv[q];
            v = v >= 0.f ? v : 0.2f * v;
            l[q] = ((mbits >> q) & 1u) ? v : -999.f;
            mx = fmaxf(mx, l[q]);
        }
#pragma unroll
        for (int o = 16; o; o >>= 1) mx = fmaxf(mx, __shfl_xor_sync(0xffffffffu, mx, o));
        float ssum = 0.f;
#pragma unroll
        for (int q = 0; q < 16; ++q) ssum += __expf(l[q] - mx);
#pragma unroll
        for (int o = 16; o; o >>= 1) ssum += __shfl_xor_sync(0xffffffffu, ssum, o);
        if (lane == 0) {
            s_rmax[rr] = mx;
            s_rinv[rr] = __fdividef(1.f, ssum);
        }
        Ms[lane * 128 + rr] = (unsigned short)mbits;   // Ms[jword][row]
    }
    __syncthreads();

    // ---- Phase C: P tiles + HMMA ----
    const int wm = warp & 3, wn = warp >> 2;
    const int r = tid >> 1, jseg = (tid & 1) * 32;
    const float srcv = s_src[r], rmaxv = s_rmax[r], rinvv = s_rinv[r];

    const int arow = (lane & 7) + ((lane >> 3) & 1) * 8;
    const int acolb = (lane >> 4) * 16;
    const int brow = (lane & 7) + (lane >> 4) * 8;
    const int bcolb = ((lane >> 3) & 1) * 16;
    const uint32_t aP0 = smu + OFF_PBH + (uint32_t)(wm * 32 + arow) * P_ROWB + acolb;
    const uint32_t bH0 = smu + OFF_HTH + (uint32_t)(wn * 32 + brow) * HT_ROWB + bcolb;

    float acc[2][4][4];
#pragma unroll
    for (int mf = 0; mf < 2; ++mf)
#pragma unroll
        for (int nf = 0; nf < 4; ++nf)
#pragma unroll
            for (int q = 0; q < 4; ++q) acc[mf][nf][q] = 0.f;

    for (int jc = 0; jc < 8; ++jc) {
        const int j0 = jc * 64;
        // compute P chunk: this thread covers row r, j in [j0+jseg, j0+jseg+32)
        {
            const int jb = j0 + jseg;
            uint32_t mw0 = Ms[(jb >> 4) * 128 + r];
            uint32_t mw1 = Ms[((jb >> 4) + 1) * 128 + r];
            uint32_t mbits = mw0 | (mw1 << 16);
#pragma unroll
            for (int q = 0; q < 32; q += 2) {
                float d0 = s_dst[jb + q];
                float d1 = s_dst[jb + q + 1];
                float l0 = srcv + d0; l0 = l0 >= 0.f ? l0 : 0.2f * l0;
                float l1 = srcv + d1; l1 = l1 >= 0.f ? l1 : 0.2f * l1;
                if (!((mbits >> q) & 1u)) l0 = -999.f;
                if (!((mbits >> (q + 1)) & 1u)) l1 = -999.f;
                float p0 = __expf(l0 - rmaxv) * rinvv;
                float p1 = __expf(l1 - rmaxv) * rinvv;
                __nv_bfloat16 h0, lo0, h1, lo1;
                split2(p0, h0, lo0);
                split2(p1, h1, lo1);
                *(__nv_bfloat162*)(Pbh + r * P_ROWB + (jseg + q) * 2) = __nv_bfloat162(h0, h1);
                *(__nv_bfloat162*)(Pbl + r * P_ROWB + (jseg + q) * 2) = __nv_bfloat162(lo0, lo1);
            }
        }
        __syncthreads();
        // HMMA over this chunk (K=64 -> 4 k16 steps)
#pragma unroll
        for (int ks = 0; ks < 4; ++ks) {
            uint32_t ah[2][4], al[2][4], bh[2][4], bl[2][4];
#pragma unroll
            for (int mf = 0; mf < 2; ++mf) {
                ldsm_x4(ah[mf], aP0 + mf * 16 * P_ROWB + ks * 32);
                ldsm_x4(al[mf], aP0 + (OFF_PBL - OFF_PBH) + mf * 16 * P_ROWB + ks * 32);
            }
#pragma unroll
            for (int nfp = 0; nfp < 2; ++nfp) {
                ldsm_x4(bh[nfp], bH0 + nfp * 16 * HT_ROWB + j0 * 2 + ks * 32);
                ldsm_x4(bl[nfp], bH0 + (OFF_HTL - OFF_HTH) + nfp * 16 * HT_ROWB + j0 * 2 + ks * 32);
            }
#pragma unroll
            for (int nfp = 0; nfp < 2; ++nfp)
#pragma unroll
                for (int hf = 0; hf < 2; ++hf) {
                    const int nf = nfp * 2 + hf;
                    const uint32_t b0h = bh[nfp][hf * 2], b1h = bh[nfp][hf * 2 + 1];
                    const uint32_t b0l = bl[nfp][hf * 2], b1l = bl[nfp][hf * 2 + 1];
#pragma unroll
                    for (int mf = 0; mf < 2; ++mf) {
                        mma16816(acc[mf][nf], ah[mf][0], ah[mf][1], ah[mf][2], ah[mf][3], b0h, b1h);
                        mma16816(acc[mf][nf], al[mf][0], al[mf][1], al[mf][2], al[mf][3], b0h, b1h);
                        mma16816(acc[mf][nf], ah[mf][0], ah[mf][1], ah[mf][2], ah[mf][3], b0l, b1l);
                    }
                }
        }
        __syncthreads();
    }

    // ---- epilogue: bias + store to g_att ----
    const int g = lane >> 2, t = lane & 3;
#pragma unroll
    for (int mf = 0; mf < 2; ++mf)
#pragma unroll
        for (int nf = 0; nf < 4; ++nf) {
            const int row = i0 + wm * 32 + mf * 16 + g;
            const int col = wn * 32 + nf * 8 + 2 * t;
            float2 bias = *(const float2*)(bbias + col);
            float2 v0 = make_float2(acc[mf][nf][0] + bias.x, acc[mf][nf][1] + bias.y);
            float2 v1 = make_float2(acc[mf][nf][2] + bias.x, acc[mf][nf][3] + bias.y);
            *(float2*)&g_att[(size_t)(b * N_ + row) * D_ + a * E_ + col] = v0;
            *(float2*)&g_att[(size_t)(b * N_ + row + 8) * D_ + a * E_ + col] = v1;
        }
}

// ---------------------------------------------------------------------------
extern "C" void kernel_launch(void* const* d_in, const int* in_sizes, int n_in,
                              void* d_out, int out_size) {
    const float* feat = (const float*)d_in[0];
    const void* adj = d_in[1];
    const float* W = (const float*)d_in[2];
    const float* bbias = (const float*)d_in[3];
    const float* wsrc = (const float*)d_in[4];
    const float* wdst = (const float*)d_in[5];
    const float* Hw = (const float*)d_in[6];
    const float* Hb = (const float*)d_in[7];
    float* out = (float*)d_out;

    detect_adj_kernel<<<1, 32>>>((const int*)adj);
    conv_feat_kernel<<<M_ * D_ / 1024, 256>>>(feat);
    conv_w1_kernel<<<D_, 256>>>(W);
    conv_w2_kernel<<<D_ * D_ / 1024, 256>>>(Hw);

    cudaFuncSetAttribute(gemm1_tc_kernel, cudaFuncAttributeMaxDynamicSharedMemorySize, GEMM_SMEM);
    cudaFuncSetAttribute(gemm2_tc_kernel, cudaFuncAttributeMaxDynamicSharedMemorySize, GEMM_SMEM);
    cudaFuncSetAttribute(attn_kernel, cudaFuncAttributeMaxDynamicSharedMemorySize, ATT_SMEM_B);

    gemm1_tc_kernel<<<dim3(D_ / 128, M_ / 128), 256, GEMM_SMEM>>>();
    srcdst_kernel<<<(B_ * A_ * N_) / 8, 256>>>(wsrc, wdst);

    attn_kernel<<<dim3(N_ / 128, A_, B_), 256, ATT_SMEM_B>>>(adj, bbias);

    gemm2_tc_kernel<<<dim3(D_ / 128, M_ / 128), 256, GEMM_SMEM>>>(feat, Hb, out);
}

// round 9
// speedup vs baseline: 1.0656x; 1.0656x over previous
#include <cuda_runtime.h>
#include <cuda_bf16.h>
#include <stdint.h>

// Problem constants
#define B_ 8
#define N_ 512
#define D_ 768
#define A_ 12
#define E_ 64
#define M_ (B_ * N_)   // 4096

// ---------------------------------------------------------------------------
// PTX helpers (all baseline features: valid for compute_103 virtual arch)
// ---------------------------------------------------------------------------
__device__ __forceinline__ uint32_t smem_u32(const void* p) {
    uint32_t a;
    asm("{ .reg .u64 t; cvta.to.shared.u64 t, %1; cvt.u32.u64 %0, t; }" : "=r"(a) : "l"(p));
    return a;
}
__device__ __forceinline__ void ldsm_x4(uint32_t* r, uint32_t addr) {
    asm volatile("ldmatrix.sync.aligned.m8n8.x4.shared.b16 {%0,%1,%2,%3}, [%4];"
        : "=r"(r[0]), "=r"(r[1]), "=r"(r[2]), "=r"(r[3]) : "r"(addr));
}
__device__ __forceinline__ void ldsm_x4_t(uint32_t* r, uint32_t addr) {
    asm volatile("ldmatrix.sync.aligned.m8n8.x4.trans.shared.b16 {%0,%1,%2,%3}, [%4];"
        : "=r"(r[0]), "=r"(r[1]), "=r"(r[2]), "=r"(r[3]) : "r"(addr));
}
#define CP16(dst, src) asm volatile("cp.async.cg.shared.global [%0], [%1], 16;" :: "r"(dst), "l"(src))
#define CP_COMMIT() asm volatile("cp.async.commit_group;" ::: "memory")
#define CP_WAIT1() asm volatile("cp.async.wait_group 1;" ::: "memory")
#define CP_WAIT0() asm volatile("cp.async.wait_group 0;" ::: "memory")

__device__ __forceinline__ void mma16816(float* c,
        uint32_t a0, uint32_t a1, uint32_t a2, uint32_t a3,
        uint32_t b0, uint32_t b1) {
    asm volatile(
        "mma.sync.aligned.m16n8k16.row.col.f32.bf16.bf16.f32 "
        "{%0,%1,%2,%3}, {%4,%5,%6,%7}, {%8,%9}, {%0,%1,%2,%3};"
        : "+f"(c[0]), "+f"(c[1]), "+f"(c[2]), "+f"(c[3])
        : "r"(a0), "r"(a1), "r"(a2), "r"(a3), "r"(b0), "r"(b1));
}

// ---------------------------------------------------------------------------
// Scratch (device globals: allocation-free)
// ---------------------------------------------------------------------------
__device__ float g_src[B_ * A_ * N_];
__device__ float g_dst[B_ * A_ * N_];
__device__ float g_att[B_ * N_ * D_];        // [b][i][a*64+e]
__device__ int   g_adj_int;
// h in bf16 hi/lo, layout [ba][j][e] (j = node, e = head dim)
__device__ __align__(16) __nv_bfloat16 g_hbh[B_ * A_ * N_ * E_];
__device__ __align__(16) __nv_bfloat16 g_hbl[B_ * A_ * N_ * E_];
// bf16 split GEMM operands (hi + lo)
__device__ __align__(16) __nv_bfloat16 g_fh[M_ * D_];
__device__ __align__(16) __nv_bfloat16 g_fl[M_ * D_];
__device__ __align__(16) __nv_bfloat16 g_w1h[D_ * D_];  // W^T: row n=a*64+e, col k=d
__device__ __align__(16) __nv_bfloat16 g_w1l[D_ * D_];
__device__ __align__(16) __nv_bfloat16 g_w2h[D_ * D_];  // Hw: row n, col k=d
__device__ __align__(16) __nv_bfloat16 g_w2l[D_ * D_];

// ---------------------------------------------------------------------------
// adj dtype detection
// ---------------------------------------------------------------------------
__global__ void detect_adj_kernel(const int* __restrict__ adj) {
    int ok = 1;
    for (int v = threadIdx.x; v < 1024; v += 32) {
        int w = adj[v];
        if (w != 0 && w != 1) ok = 0;
    }
#pragma unroll
    for (int o = 16; o; o >>= 1) ok &= __shfl_xor_sync(0xffffffffu, ok, o);
    if (threadIdx.x == 0) g_adj_int = ok;
}

// ---------------------------------------------------------------------------
// fp32 -> bf16 hi/lo split conversions
// ---------------------------------------------------------------------------
__device__ __forceinline__ void split2(float x, __nv_bfloat16& h, __nv_bfloat16& l) {
    h = __float2bfloat16(x);
    l = __float2bfloat16(x - __bfloat162float(h));
}

__global__ void conv_feat_kernel(const float* __restrict__ f) {
    const int g4 = (blockIdx.x * 256 + threadIdx.x) * 4;
    float4 v = *(const float4*)(f + g4);
    __nv_bfloat16 h0, h1, h2, h3, l0, l1, l2, l3;
    split2(v.x, h0, l0); split2(v.y, h1, l1); split2(v.z, h2, l2); split2(v.w, h3, l3);
    ((__nv_bfloat162*)(g_fh + g4))[0] = __nv_bfloat162(h0, h1);
    ((__nv_bfloat162*)(g_fh + g4))[1] = __nv_bfloat162(h2, h3);
    ((__nv_bfloat162*)(g_fl + g4))[0] = __nv_bfloat162(l0, l1);
    ((__nv_bfloat162*)(g_fl + g4))[1] = __nv_bfloat162(l2, l3);
}

__global__ void conv_w1_kernel(const float* __restrict__ W) {
    const int n = blockIdx.x;
    const int a = n >> 6, e = n & 63;
    for (int d = threadIdx.x; d < D_; d += 256) {
        float x = W[(a * D_ + d) * E_ + e];
        __nv_bfloat16 h, l;
        split2(x, h, l);
        g_w1h[n * D_ + d] = h;
        g_w1l[n * D_ + d] = l;
    }
}

__global__ void conv_w2_kernel(const float* __restrict__ Hw) {
    const int g4 = (blockIdx.x * 256 + threadIdx.x) * 4;
    float4 v = *(const float4*)(Hw + g4);
    __nv_bfloat16 h0, h1, h2, h3, l0, l1, l2, l3;
    split2(v.x, h0, l0); split2(v.y, h1, l1); split2(v.z, h2, l2); split2(v.w, h3, l3);
    ((__nv_bfloat162*)(g_w2h + g4))[0] = __nv_bfloat162(h0, h1);
    ((__nv_bfloat162*)(g_w2h + g4))[1] = __nv_bfloat162(h2, h3);
    ((__nv_bfloat162*)(g_w2l + g4))[0] = __nv_bfloat162(l0, l1);
    ((__nv_bfloat162*)(g_w2l + g4))[1] = __nv_bfloat162(l2, l3);
}

// ---------------------------------------------------------------------------
// HMMA bf16x3 GEMM: 128x128 block, 8 warps (4m x 2n), warp 32x64.
// K chunks of 32; cp.async double buffer; ldmatrix fragment loads.
// ---------------------------------------------------------------------------
#define KC_ 32
#define NKC_ (D_ / KC_)          // 24
#define TROW_B 80                // bytes per smem tile row (32 bf16 + 8 pad)
#define TILE_B (128 * TROW_B)    // 10240
#define BUF_B (4 * TILE_B)       // 40960 (Ah,Al,Bh,Bl)
#define GEMM_SMEM (2 * BUF_B)    // 81920

__device__ __forceinline__ void hmma_mainloop(
        float acc[2][8][4],
        const __nv_bfloat16* __restrict__ Ah, const __nv_bfloat16* __restrict__ Al,
        const __nv_bfloat16* __restrict__ Bh, const __nv_bfloat16* __restrict__ Bl,
        int m0, int n0, char* sm) {
    const int tid = threadIdx.x;
    const int warp = tid >> 5, lane = tid & 31;
    const int wm = warp & 3, wn = warp >> 2;

    const int lr = tid >> 1;
    const int lce = (tid & 1) * 16;
    const uint32_t sto = (uint32_t)lr * TROW_B + (tid & 1) * 32;
    const uint32_t smu = smem_u32(sm);

    const __nv_bfloat16* pAh = Ah + (size_t)(m0 + lr) * D_ + lce;
    const __nv_bfloat16* pAl = Al + (size_t)(m0 + lr) * D_ + lce;
    const __nv_bfloat16* pBh = Bh + (size_t)(n0 + lr) * D_ + lce;
    const __nv_bfloat16* pBl = Bl + (size_t)(n0 + lr) * D_ + lce;

#define ISSUE(kc, buf) do {                                                  \
    uint32_t _bb = smu + (buf) * BUF_B + sto;                                \
    const int _o = (kc) * KC_;                                               \
    CP16(_bb, pAh + _o);                 CP16(_bb + 16, pAh + _o + 8);       \
    CP16(_bb + TILE_B, pAl + _o);        CP16(_bb + TILE_B + 16, pAl + _o + 8); \
    CP16(_bb + 2 * TILE_B, pBh + _o);    CP16(_bb + 2 * TILE_B + 16, pBh + _o + 8); \
    CP16(_bb + 3 * TILE_B, pBl + _o);    CP16(_bb + 3 * TILE_B + 16, pBl + _o + 8); \
    CP_COMMIT(); } while (0)

    ISSUE(0, 0);

    // ldmatrix address components
    const int arow = (lane & 7) + ((lane >> 3) & 1) * 8;
    const int acolb = (lane >> 4) * 16;
    const int brow = (lane & 7) + (lane >> 4) * 8;
    const int bcolb = ((lane >> 3) & 1) * 16;

    for (int kc = 0; kc < NKC_; ++kc) {
        if (kc + 1 < NKC_) { ISSUE(kc + 1, (kc + 1) & 1); CP_WAIT1(); }
        else               { CP_WAIT0(); }
        __syncthreads();
        const uint32_t bufb = smu + (kc & 1) * BUF_B;
        const uint32_t aA0 = bufb + (uint32_t)(wm * 32 + arow) * TROW_B + acolb;
        const uint32_t bB0 = bufb + 2 * TILE_B + (uint32_t)(wn * 64 + brow) * TROW_B + bcolb;
#pragma unroll
        for (int ks = 0; ks < 2; ++ks) {
            uint32_t ah[2][4], al[2][4], bh[4][4], bl[4][4];
#pragma unroll
            for (int mf = 0; mf < 2; ++mf) {
                ldsm_x4(ah[mf], aA0 + mf * 16 * TROW_B + ks * 32);
                ldsm_x4(al[mf], aA0 + TILE_B + mf * 16 * TROW_B + ks * 32);
            }
#pragma unroll
            for (int nfp = 0; nfp < 4; ++nfp) {
                ldsm_x4(bh[nfp], bB0 + nfp * 16 * TROW_B + ks * 32);
                ldsm_x4(bl[nfp], bB0 + TILE_B + nfp * 16 * TROW_B + ks * 32);
            }
#pragma unroll
            for (int nfp = 0; nfp < 4; ++nfp)
#pragma unroll
                for (int hf = 0; hf < 2; ++hf) {
                    const int nf = nfp * 2 + hf;
                    const uint32_t b0h = bh[nfp][hf * 2], b1h = bh[nfp][hf * 2 + 1];
                    const uint32_t b0l = bl[nfp][hf * 2], b1l = bl[nfp][hf * 2 + 1];
#pragma unroll
                    for (int mf = 0; mf < 2; ++mf) {
                        mma16816(acc[mf][nf], ah[mf][0], ah[mf][1], ah[mf][2], ah[mf][3], b0h, b1h);
                        mma16816(acc[mf][nf], al[mf][0], al[mf][1], al[mf][2], al[mf][3], b0h, b1h);
                        mma16816(acc[mf][nf], ah[mf][0], ah[mf][1], ah[mf][2], ah[mf][3], b0l, b1l);
                    }
                }
        }
        __syncthreads();
    }
#undef ISSUE
}

// ---------------------------------------------------------------------------
// GEMM-1 (HMMA): h = feat @ W^T.
// Epilogue: (a) split h to bf16 hi/lo -> g_hbh/g_hbl [ba][j][e];
//           (b) fused src/dst logits: tanh(h) . w_src/w_dst per row.
// ---------------------------------------------------------------------------
__global__ __launch_bounds__(256) void gemm1_tc_kernel(const float* __restrict__ wsrc,
                                                       const float* __restrict__ wdst) {
    extern __shared__ char sm[];
    const int m0 = blockIdx.y << 7;
    const int n0 = blockIdx.x << 7;
    float acc[2][8][4];
#pragma unroll
    for (int mf = 0; mf < 2; ++mf)
#pragma unroll
        for (int nf = 0; nf < 8; ++nf)
#pragma unroll
            for (int q = 0; q < 4; ++q) acc[mf][nf][q] = 0.f;

    hmma_mainloop(acc, g_fh, g_fl, g_w1h, g_w1l, m0, n0, sm);

    const int warp = threadIdx.x >> 5, lane = threadIdx.x & 31;
    const int wm = warp & 3, wn = warp >> 2;
    const int g = lane >> 2, t = lane & 3;
    const int head = (n0 >> 6) + wn;

    float sd[2][2], dd[2][2];   // [mf][rowhalf]
#pragma unroll
    for (int mf = 0; mf < 2; ++mf) sd[mf][0] = sd[mf][1] = dd[mf][0] = dd[mf][1] = 0.f;

#pragma unroll
    for (int mf = 0; mf < 2; ++mf) {
        const int m = m0 + wm * 32 + mf * 16 + g;
        const int b = m >> 9, i = m & (N_ - 1);
        const int ba = b * A_ + head;
#pragma unroll
        for (int nf = 0; nf < 8; ++nf) {
            const int e = nf * 8 + 2 * t;
            // bf16 split store [ba][j][e]
            __nv_bfloat16 h0, l0, h1, l1;
            split2(acc[mf][nf][0], h0, l0);
            split2(acc[mf][nf][1], h1, l1);
            *(__nv_bfloat162*)&g_hbh[((size_t)(ba * N_ + i)) * E_ + e] = __nv_bfloat162(h0, h1);
            *(__nv_bfloat162*)&g_hbl[((size_t)(ba * N_ + i)) * E_ + e] = __nv_bfloat162(l0, l1);
            split2(acc[mf][nf][2], h0, l0);
            split2(acc[mf][nf][3], h1, l1);
            *(__nv_bfloat162*)&g_hbh[((size_t)(ba * N_ + i + 8)) * E_ + e] = __nv_bfloat162(h0, h1);
            *(__nv_bfloat162*)&g_hbl[((size_t)(ba * N_ + i + 8)) * E_ + e] = __nv_bfloat162(l0, l1);
            // fused src/dst partial dots
            float2 ws = *(const float2*)(wsrc + head * E_ + e);
            float2 wd = *(const float2*)(wdst + head * E_ + e);
            float t0 = tanhf(acc[mf][nf][0]), t1 = tanhf(acc[mf][nf][1]);
            float t2 = tanhf(acc[mf][nf][2]), t3 = tanhf(acc[mf][nf][3]);
            sd[mf][0] += t0 * ws.x + t1 * ws.y;
            sd[mf][1] += t2 * ws.x + t3 * ws.y;
            dd[mf][0] += t0 * wd.x + t1 * wd.y;
            dd[mf][1] += t2 * wd.x + t3 * wd.y;
        }
#pragma unroll
        for (int rh = 0; rh < 2; ++rh) {
            float s = sd[mf][rh], d = dd[mf][rh];
            s += __shfl_xor_sync(0xffffffffu, s, 1);
            s += __shfl_xor_sync(0xffffffffu, s, 2);
            d += __shfl_xor_sync(0xffffffffu, d, 1);
            d += __shfl_xor_sync(0xffffffffu, d, 2);
            if (t == 0) {
                g_src[ba * N_ + i + rh * 8] = s;
                g_dst[ba * N_ + i + rh * 8] = d;
            }
        }
    }
}

// ---------------------------------------------------------------------------
// GEMM-2 (HMMA) + fused epilogue:
// gate = sigmoid(feat @ Hw^T + Hb); out = gate*elu(g_att) + (1-gate)*feat
// ---------------------------------------------------------------------------
__device__ __forceinline__ float blend_one(float accv, float hb, float att, float f) {
    float gt = 1.f / (1.f + __expf(-(accv + hb)));
    float fo = att > 0.f ? att : (__expf(att) - 1.f);
    return gt * fo + (1.f - gt) * f;
}

__global__ __launch_bounds__(256) void gemm2_tc_kernel(const float* __restrict__ feat,
                                                       const float* __restrict__ Hb,
                                                       float* __restrict__ out) {
    extern __shared__ char sm[];
    const int m0 = blockIdx.y << 7;
    const int n0 = blockIdx.x << 7;
    float acc[2][8][4];
#pragma unroll
    for (int mf = 0; mf < 2; ++mf)
#pragma unroll
        for (int nf = 0; nf < 8; ++nf)
#pragma unroll
            for (int q = 0; q < 4; ++q) acc[mf][nf][q] = 0.f;

    hmma_mainloop(acc, g_fh, g_fl, g_w2h, g_w2l, m0, n0, sm);

    const int warp = threadIdx.x >> 5, lane = threadIdx.x & 31;
    const int wm = warp & 3, wn = warp >> 2;
    const int g = lane >> 2, t = lane & 3;
#pragma unroll
    for (int mf = 0; mf < 2; ++mf)
#pragma unroll
        for (int nf = 0; nf < 8; ++nf) {
            const int m = m0 + wm * 32 + mf * 16 + g;
            const int n = n0 + wn * 64 + nf * 8 + 2 * t;
            float2 hb = *(const float2*)(Hb + n);
#pragma unroll
            for (int rr = 0; rr < 2; ++rr) {
                const int mm = m + rr * 8;
                float2 av = *(const float2*)(g_att + (size_t)mm * D_ + n);
                float2 fv = *(const float2*)(feat + (size_t)mm * D_ + n);
                float2 ov;
                ov.x = blend_one(acc[mf][nf][rr * 2 + 0], hb.x, av.x, fv.x);
                ov.y = blend_one(acc[mf][nf][rr * 2 + 1], hb.y, av.y, fv.y);
                *(float2*)(out + (size_t)mm * D_ + n) = ov;
            }
        }
}

// ---------------------------------------------------------------------------
// Attention (HMMA): block = (itile of 128, a, b), 8 warps.
// Phase A: cp.async copy of pre-split h (bf16 hi/lo, [j][e]) into smem.
// Phase B: warp-per-row softmax stats (max, 1/sum) + packed mask bits.
// Phase C: 8 chunks of 64 j: recompute P -> bf16 hi/lo tile, then
//          HMMA  Ph@Hh + Pl@Hh + Ph@Hl; B-frags via ldmatrix.trans.
// ---------------------------------------------------------------------------
#define HT_ROWB 144              // 64 bf16 + 16B pad (per j row)
#define P_ROWB 144               // 64 bf16 + pad
#define OFF_HTH 0
#define OFF_HTL (512 * HT_ROWB)              // 73728
#define OFF_PBH (2 * 512 * HT_ROWB)          // 147456
#define OFF_PBL (OFF_PBH + 128 * P_ROWB)     // 165888
#define OFF_SRC (OFF_PBL + 128 * P_ROWB)     // 184320
#define OFF_DST (OFF_SRC + 512)              // 184832
#define OFF_RMX (OFF_DST + 2048)             // 186880
#define OFF_RIV (OFF_RMX + 512)              // 187392
#define OFF_MS  (OFF_RIV + 512)              // 187904
#define ATT_SMEM_B (OFF_MS + 8192)           // 196096

__global__ __launch_bounds__(256) void attn_kernel(const void* __restrict__ adjv,
                                                   const float* __restrict__ bbias) {
    extern __shared__ char sm[];
    const uint32_t smu = smem_u32(sm);
    char* Pbh = sm + OFF_PBH;
    char* Pbl = sm + OFF_PBL;
    float* s_src = (float*)(sm + OFF_SRC);
    float* s_dst = (float*)(sm + OFF_DST);
    float* s_rmax = (float*)(sm + OFF_RMX);
    float* s_rinv = (float*)(sm + OFF_RIV);
    unsigned short* Ms = (unsigned short*)(sm + OFF_MS);   // [32 jwords][128 rows]

    const int tid = threadIdx.x;
    const int lane = tid & 31, warp = tid >> 5;
    const int b = blockIdx.z, a = blockIdx.y, it = blockIdx.x;
    const int ba = b * A_ + a;
    const int i0 = it * 128;

    // ---- Phase A: cp.async copy of pre-split h; load vectors ----
    {
        const __nv_bfloat16* srcH = g_hbh + (size_t)ba * N_ * E_;
        const __nv_bfloat16* srcL = g_hbl + (size_t)ba * N_ * E_;
#pragma unroll
        for (int c = 0; c < 16; ++c) {
            const int idx = tid + c * 256;          // 4096 chunks of 16B
            const int j = idx >> 3, q = idx & 7;
            const uint32_t dst = smu + OFF_HTH + (uint32_t)j * HT_ROWB + q * 16;
            CP16(dst, srcH + j * E_ + q * 8);
            CP16(dst + OFF_HTL, srcL + j * E_ + q * 8);
        }
        CP_COMMIT();
        if (tid < 128) s_src[tid] = g_src[ba * N_ + i0 + tid];
        s_dst[tid] = g_dst[ba * N_ + tid];
        s_dst[tid + 256] = g_dst[ba * N_ + tid + 256];
        CP_WAIT0();
    }
    __syncthreads();

    // ---- Phase B: stats (warp per row), packed mask bits ----
    const int adj_int = g_adj_int;
    for (int rr = warp; rr < 128; rr += 8) {
        const size_t rowoff = (size_t)(b * N_ + i0 + rr) * N_;
        unsigned mbits = 0;
        if (adj_int) {
            const uint4* ap = (const uint4*)((const int*)adjv + rowoff + lane * 16);
#pragma unroll
            for (int q = 0; q < 4; ++q) {
                uint4 w = ap[q];
                mbits |= (w.x ? 1u : 0u) << (q * 4 + 0);
                mbits |= (w.y ? 1u : 0u) << (q * 4 + 1);
                mbits |= (w.z ? 1u : 0u) << (q * 4 + 2);
                mbits |= (w.w ? 1u : 0u) << (q * 4 + 3);
            }
        } else {
            uint4 w = *(const uint4*)((const uint8_t*)adjv + rowoff + lane * 16);
            unsigned ws[4] = {w.x, w.y, w.z, w.w};
#pragma unroll
            for (int q = 0; q < 4; ++q)
#pragma unroll
                for (int bq = 0; bq < 4; ++bq)
                    mbits |= (((ws[q] >> (8 * bq)) & 0xffu) ? 1u : 0u) << (q * 4 + bq);
        }
        const float sbase = s_src[rr];
        alignas(16) float dv[16];
#pragma unroll
        for (int c = 0; c < 4; ++c)
            *(float4*)&dv[c * 4] = *(const float4*)&s_dst[lane * 16 + c * 4];
        float l[16];
        float mx = -1e30f;
#pragma unroll
        for (int q = 0; q < 16; ++q) {
            float v = sbase + dv[q];
            v = v >= 0.f ? v : 0.2f * v;
            l[q] = ((mbits >> q) & 1u) ? v : -999.f;
            mx = fmaxf(mx, l[q]);
        }
#pragma unroll
        for (int o = 16; o; o >>= 1) mx = fmaxf(mx, __shfl_xor_sync(0xffffffffu, mx, o));
        float ssum = 0.f;
#pragma unroll
        for (int q = 0; q < 16; ++q) ssum += __expf(l[q] - mx);
#pragma unroll
        for (int o = 16; o; o >>= 1) ssum += __shfl_xor_sync(0xffffffffu, ssum, o);
        if (lane == 0) {
            s_rmax[rr] = mx;
            s_rinv[rr] = __fdividef(1.f, ssum);
        }
        Ms[lane * 128 + rr] = (unsigned short)mbits;   // Ms[jword][row]
    }
    __syncthreads();

    // ---- Phase C: P tiles + HMMA ----
    const int wm = warp & 3, wn = warp >> 2;
    const int r = tid >> 1, jseg = (tid & 1) * 32;
    const float srcv = s_src[r], rmaxv = s_rmax[r], rinvv = s_rinv[r];

    // A (P) fragments: non-trans, rows = i
    const int arow = (lane & 7) + ((lane >> 3) & 1) * 8;
    const int acolb = (lane >> 4) * 16;
    const uint32_t aP0 = smu + OFF_PBH + (uint32_t)(wm * 32 + arow) * P_ROWB + acolb;
    // B (H) fragments: trans ldmatrix on [j][e] storage
    const int jrow = lane & 15;
    const int ecolb = (lane >> 4) * 16;
    const uint32_t bH0 = smu + OFF_HTH + (uint32_t)jrow * HT_ROWB + (wn * 32) * 2 + ecolb;

    float acc[2][4][4];
#pragma unroll
    for (int mf = 0; mf < 2; ++mf)
#pragma unroll
        for (int nf = 0; nf < 4; ++nf)
#pragma unroll
            for (int q = 0; q < 4; ++q) acc[mf][nf][q] = 0.f;

    for (int jc = 0; jc < 8; ++jc) {
        const int j0 = jc * 64;
        // compute P chunk: this thread covers row r, j in [j0+jseg, j0+jseg+32)
        {
            const int jb = j0 + jseg;
            uint32_t mw0 = Ms[(jb >> 4) * 128 + r];
            uint32_t mw1 = Ms[((jb >> 4) + 1) * 128 + r];
            uint32_t mbits = mw0 | (mw1 << 16);
#pragma unroll
            for (int q = 0; q < 32; q += 2) {
                float d0 = s_dst[jb + q];
                float d1 = s_dst[jb + q + 1];
                float l0 = srcv + d0; l0 = l0 >= 0.f ? l0 : 0.2f * l0;
                float l1 = srcv + d1; l1 = l1 >= 0.f ? l1 : 0.2f * l1;
                if (!((mbits >> q) & 1u)) l0 = -999.f;
                if (!((mbits >> (q + 1)) & 1u)) l1 = -999.f;
                float p0 = __expf(l0 - rmaxv) * rinvv;
                float p1 = __expf(l1 - rmaxv) * rinvv;
                __nv_bfloat16 h0, lo0, h1, lo1;
                split2(p0, h0, lo0);
                split2(p1, h1, lo1);
                *(__nv_bfloat162*)(Pbh + r * P_ROWB + (jseg + q) * 2) = __nv_bfloat162(h0, h1);
                *(__nv_bfloat162*)(Pbl + r * P_ROWB + (jseg + q) * 2) = __nv_bfloat162(lo0, lo1);
            }
        }
        __syncthreads();
        // HMMA over this chunk (K=64 -> 4 k16 steps)
#pragma unroll
        for (int ks = 0; ks < 4; ++ks) {
            uint32_t ah[2][4], al[2][4], bh[2][4], bl[2][4];
#pragma unroll
            for (int mf = 0; mf < 2; ++mf) {
                ldsm_x4(ah[mf], aP0 + mf * 16 * P_ROWB + ks * 32);
                ldsm_x4(al[mf], aP0 + (OFF_PBL - OFF_PBH) + mf * 16 * P_ROWB + ks * 32);
            }
            const uint32_t bbase = bH0 + (uint32_t)(j0 + ks * 16) * HT_ROWB;
#pragma unroll
            for (int nfp = 0; nfp < 2; ++nfp) {
                ldsm_x4_t(bh[nfp], bbase + nfp * 32);
                ldsm_x4_t(bl[nfp], bbase + OFF_HTL + nfp * 32);
            }
#pragma unroll
            for (int nfp = 0; nfp < 2; ++nfp)
#pragma unroll
                for (int hf = 0; hf < 2; ++hf) {
                    const int nf = nfp * 2 + hf;
                    const uint32_t b0h = bh[nfp][hf * 2], b1h = bh[nfp][hf * 2 + 1];
                    const uint32_t b0l = bl[nfp][hf * 2], b1l = bl[nfp][hf * 2 + 1];
#pragma unroll
                    for (int mf = 0; mf < 2; ++mf) {
                        mma16816(acc[mf][nf], ah[mf][0], ah[mf][1], ah[mf][2], ah[mf][3], b0h, b1h);
                        mma16816(acc[mf][nf], al[mf][0], al[mf][1], al[mf][2], al[mf][3], b0h, b1h);
                        mma16816(acc[mf][nf], ah[mf][0], ah[mf][1], ah[mf][2], ah[mf][3], b0l, b1l);
                    }
                }
        }
        __syncthreads();
    }

    // ---- epilogue: bias + store to g_att ----
    const int g = lane >> 2, t = lane & 3;
#pragma unroll
    for (int mf = 0; mf < 2; ++mf)
#pragma unroll
        for (int nf = 0; nf < 4; ++nf) {
            const int row = i0 + wm * 32 + mf * 16 + g;
            const int col = wn * 32 + nf * 8 + 2 * t;
            float2 bias = *(const float2*)(bbias + col);
            float2 v0 = make_float2(acc[mf][nf][0] + bias.x, acc[mf][nf][1] + bias.y);
            float2 v1 = make_float2(acc[mf][nf][2] + bias.x, acc[mf][nf][3] + bias.y);
            *(float2*)&g_att[(size_t)(b * N_ + row) * D_ + a * E_ + col] = v0;
            *(float2*)&g_att[(size_t)(b * N_ + row + 8) * D_ + a * E_ + col] = v1;
        }
}

// ---------------------------------------------------------------------------
extern "C" void kernel_launch(void* const* d_in, const int* in_sizes, int n_in,
                              void* d_out, int out_size) {
    const float* feat = (const float*)d_in[0];
    const void* adj = d_in[1];
    const float* W = (const float*)d_in[2];
    const float* bbias = (const float*)d_in[3];
    const float* wsrc = (const float*)d_in[4];
    const float* wdst = (const float*)d_in[5];
    const float* Hw = (const float*)d_in[6];
    const float* Hb = (const float*)d_in[7];
    float* out = (float*)d_out;

    detect_adj_kernel<<<1, 32>>>((const int*)adj);
    conv_feat_kernel<<<M_ * D_ / 1024, 256>>>(feat);
    conv_w1_kernel<<<D_, 256>>>(W);
    conv_w2_kernel<<<D_ * D_ / 1024, 256>>>(Hw);

    cudaFuncSetAttribute(gemm1_tc_kernel, cudaFuncAttributeMaxDynamicSharedMemorySize, GEMM_SMEM);
    cudaFuncSetAttribute(gemm2_tc_kernel, cudaFuncAttributeMaxDynamicSharedMemorySize, GEMM_SMEM);
    cudaFuncSetAttribute(attn_kernel, cudaFuncAttributeMaxDynamicSharedMemorySize, ATT_SMEM_B);

    gemm1_tc_kernel<<<dim3(D_ / 128, M_ / 128), 256, GEMM_SMEM>>>(wsrc, wdst);

    attn_kernel<<<dim3(N_ / 128, A_, B_), 256, ATT_SMEM_B>>>(adj, bbias);

    gemm2_tc_kernel<<<dim3(D_ / 128, M_ / 128), 256, GEMM_SMEM>>>(feat, Hb, out);
}

// round 10
// speedup vs baseline: 1.2005x; 1.1267x over previous
#include <cuda_runtime.h>
#include <cuda_bf16.h>
#include <stdint.h>

// Problem constants
#define B_ 8
#define N_ 512
#define D_ 768
#define A_ 12
#define E_ 64
#define M_ (B_ * N_)   // 4096

// ---------------------------------------------------------------------------
// PTX helpers (all baseline features: valid for compute_103 virtual arch)
// ---------------------------------------------------------------------------
__device__ __forceinline__ uint32_t smem_u32(const void* p) {
    uint32_t a;
    asm("{ .reg .u64 t; cvta.to.shared.u64 t, %1; cvt.u32.u64 %0, t; }" : "=r"(a) : "l"(p));
    return a;
}
__device__ __forceinline__ void ldsm_x4(uint32_t* r, uint32_t addr) {
    asm volatile("ldmatrix.sync.aligned.m8n8.x4.shared.b16 {%0,%1,%2,%3}, [%4];"
        : "=r"(r[0]), "=r"(r[1]), "=r"(r[2]), "=r"(r[3]) : "r"(addr));
}
__device__ __forceinline__ void ldsm_x4_t(uint32_t* r, uint32_t addr) {
    asm volatile("ldmatrix.sync.aligned.m8n8.x4.trans.shared.b16 {%0,%1,%2,%3}, [%4];"
        : "=r"(r[0]), "=r"(r[1]), "=r"(r[2]), "=r"(r[3]) : "r"(addr));
}
#define CP16(dst, src) asm volatile("cp.async.cg.shared.global [%0], [%1], 16;" :: "r"(dst), "l"(src))
#define CP_COMMIT() asm volatile("cp.async.commit_group;" ::: "memory")
#define CP_WAIT1() asm volatile("cp.async.wait_group 1;" ::: "memory")
#define CP_WAIT0() asm volatile("cp.async.wait_group 0;" ::: "memory")

__device__ __forceinline__ void mma16816(float* c,
        uint32_t a0, uint32_t a1, uint32_t a2, uint32_t a3,
        uint32_t b0, uint32_t b1) {
    asm volatile(
        "mma.sync.aligned.m16n8k16.row.col.f32.bf16.bf16.f32 "
        "{%0,%1,%2,%3}, {%4,%5,%6,%7}, {%8,%9}, {%0,%1,%2,%3};"
        : "+f"(c[0]), "+f"(c[1]), "+f"(c[2]), "+f"(c[3])
        : "r"(a0), "r"(a1), "r"(a2), "r"(a3), "r"(b0), "r"(b1));
}

// ---------------------------------------------------------------------------
// Scratch (device globals: allocation-free)
// ---------------------------------------------------------------------------
__device__ float g_src[B_ * A_ * N_];
__device__ float g_dst[B_ * A_ * N_];
__device__ float g_att[B_ * N_ * D_];        // [b][i][a*64+e]
__device__ int   g_adj_int;
// h in bf16 hi/lo, layout [ba][j][e] (j = node, e = head dim)
__device__ __align__(16) __nv_bfloat16 g_hbh[B_ * A_ * N_ * E_];
__device__ __align__(16) __nv_bfloat16 g_hbl[B_ * A_ * N_ * E_];
// bf16 split GEMM operands (hi + lo)
__device__ __align__(16) __nv_bfloat16 g_fh[M_ * D_];
__device__ __align__(16) __nv_bfloat16 g_fl[M_ * D_];
__device__ __align__(16) __nv_bfloat16 g_w1h[D_ * D_];  // W^T: row n=a*64+e, col k=d
__device__ __align__(16) __nv_bfloat16 g_w1l[D_ * D_];
__device__ __align__(16) __nv_bfloat16 g_w2h[D_ * D_];  // Hw: row n, col k=d
__device__ __align__(16) __nv_bfloat16 g_w2l[D_ * D_];

// ---------------------------------------------------------------------------
// adj dtype detection
// ---------------------------------------------------------------------------
__global__ void detect_adj_kernel(const int* __restrict__ adj) {
    int ok = 1;
    for (int v = threadIdx.x; v < 1024; v += 32) {
        int w = adj[v];
        if (w != 0 && w != 1) ok = 0;
    }
#pragma unroll
    for (int o = 16; o; o >>= 1) ok &= __shfl_xor_sync(0xffffffffu, ok, o);
    if (threadIdx.x == 0) g_adj_int = ok;
}

// ---------------------------------------------------------------------------
// fp32 -> bf16 hi/lo split conversions
// ---------------------------------------------------------------------------
__device__ __forceinline__ void split2(float x, __nv_bfloat16& h, __nv_bfloat16& l) {
    h = __float2bfloat16(x);
    l = __float2bfloat16(x - __bfloat162float(h));
}

__global__ void conv_feat_kernel(const float* __restrict__ f) {
    const int g4 = (blockIdx.x * 256 + threadIdx.x) * 4;
    float4 v = *(const float4*)(f + g4);
    __nv_bfloat16 h0, h1, h2, h3, l0, l1, l2, l3;
    split2(v.x, h0, l0); split2(v.y, h1, l1); split2(v.z, h2, l2); split2(v.w, h3, l3);
    ((__nv_bfloat162*)(g_fh + g4))[0] = __nv_bfloat162(h0, h1);
    ((__nv_bfloat162*)(g_fh + g4))[1] = __nv_bfloat162(h2, h3);
    ((__nv_bfloat162*)(g_fl + g4))[0] = __nv_bfloat162(l0, l1);
    ((__nv_bfloat162*)(g_fl + g4))[1] = __nv_bfloat162(l2, l3);
}

// W [a][d][e] -> W^T rows n=a*64+e, cols d; smem-transpose for coalescing.
__global__ void conv_w1_kernel(const float* __restrict__ W) {
    __shared__ float tile[64][65];
    const int a = blockIdx.x, d0 = blockIdx.y * 64;
    const int tid = threadIdx.x;
#pragma unroll
    for (int it = 0; it < 16; ++it) {
        const int idx = it * 256 + tid;
        const int dd = idx >> 6, e = idx & 63;
        tile[dd][e] = W[(a * D_ + d0 + dd) * E_ + e];
    }
    __syncthreads();
#pragma unroll
    for (int it = 0; it < 16; ++it) {
        const int idx = it * 256 + tid;
        const int e = idx >> 6, dd = idx & 63;
        __nv_bfloat16 h, l;
        split2(tile[dd][e], h, l);
        g_w1h[(a * 64 + e) * D_ + d0 + dd] = h;
        g_w1l[(a * 64 + e) * D_ + d0 + dd] = l;
    }
}

__global__ void conv_w2_kernel(const float* __restrict__ Hw) {
    const int g4 = (blockIdx.x * 256 + threadIdx.x) * 4;
    float4 v = *(const float4*)(Hw + g4);
    __nv_bfloat16 h0, h1, h2, h3, l0, l1, l2, l3;
    split2(v.x, h0, l0); split2(v.y, h1, l1); split2(v.z, h2, l2); split2(v.w, h3, l3);
    ((__nv_bfloat162*)(g_w2h + g4))[0] = __nv_bfloat162(h0, h1);
    ((__nv_bfloat162*)(g_w2h + g4))[1] = __nv_bfloat162(h2, h3);
    ((__nv_bfloat162*)(g_w2l + g4))[0] = __nv_bfloat162(l0, l1);
    ((__nv_bfloat162*)(g_w2l + g4))[1] = __nv_bfloat162(l2, l3);
}

// ---------------------------------------------------------------------------
// HMMA bf16x3 GEMM: 128x128 block, 8 warps (4m x 2n), warp 32x64.
// ---------------------------------------------------------------------------
#define KC_ 32
#define NKC_ (D_ / KC_)          // 24
#define TROW_B 80
#define TILE_B (128 * TROW_B)    // 10240
#define BUF_B (4 * TILE_B)       // 40960
#define GEMM_SMEM (2 * BUF_B)    // 81920

__device__ __forceinline__ void hmma_mainloop(
        float acc[2][8][4],
        const __nv_bfloat16* __restrict__ Ah, const __nv_bfloat16* __restrict__ Al,
        const __nv_bfloat16* __restrict__ Bh, const __nv_bfloat16* __restrict__ Bl,
        int m0, int n0, char* sm) {
    const int tid = threadIdx.x;
    const int warp = tid >> 5, lane = tid & 31;
    const int wm = warp & 3, wn = warp >> 2;

    const int lr = tid >> 1;
    const int lce = (tid & 1) * 16;
    const uint32_t sto = (uint32_t)lr * TROW_B + (tid & 1) * 32;
    const uint32_t smu = smem_u32(sm);

    const __nv_bfloat16* pAh = Ah + (size_t)(m0 + lr) * D_ + lce;
    const __nv_bfloat16* pAl = Al + (size_t)(m0 + lr) * D_ + lce;
    const __nv_bfloat16* pBh = Bh + (size_t)(n0 + lr) * D_ + lce;
    const __nv_bfloat16* pBl = Bl + (size_t)(n0 + lr) * D_ + lce;

#define ISSUE(kc, buf) do {                                                  \
    uint32_t _bb = smu + (buf) * BUF_B + sto;                                \
    const int _o = (kc) * KC_;                                               \
    CP16(_bb, pAh + _o);                 CP16(_bb + 16, pAh + _o + 8);       \
    CP16(_bb + TILE_B, pAl + _o);        CP16(_bb + TILE_B + 16, pAl + _o + 8); \
    CP16(_bb + 2 * TILE_B, pBh + _o);    CP16(_bb + 2 * TILE_B + 16, pBh + _o + 8); \
    CP16(_bb + 3 * TILE_B, pBl + _o);    CP16(_bb + 3 * TILE_B + 16, pBl + _o + 8); \
    CP_COMMIT(); } while (0)

    ISSUE(0, 0);

    const int arow = (lane & 7) + ((lane >> 3) & 1) * 8;
    const int acolb = (lane >> 4) * 16;
    const int brow = (lane & 7) + (lane >> 4) * 8;
    const int bcolb = ((lane >> 3) & 1) * 16;

    for (int kc = 0; kc < NKC_; ++kc) {
        if (kc + 1 < NKC_) { ISSUE(kc + 1, (kc + 1) & 1); CP_WAIT1(); }
        else               { CP_WAIT0(); }
        __syncthreads();
        const uint32_t bufb = smu + (kc & 1) * BUF_B;
        const uint32_t aA0 = bufb + (uint32_t)(wm * 32 + arow) * TROW_B + acolb;
        const uint32_t bB0 = bufb + 2 * TILE_B + (uint32_t)(wn * 64 + brow) * TROW_B + bcolb;
#pragma unroll
        for (int ks = 0; ks < 2; ++ks) {
            uint32_t ah[2][4], al[2][4], bh[4][4], bl[4][4];
#pragma unroll
            for (int mf = 0; mf < 2; ++mf) {
                ldsm_x4(ah[mf], aA0 + mf * 16 * TROW_B + ks * 32);
                ldsm_x4(al[mf], aA0 + TILE_B + mf * 16 * TROW_B + ks * 32);
            }
#pragma unroll
            for (int nfp = 0; nfp < 4; ++nfp) {
                ldsm_x4(bh[nfp], bB0 + nfp * 16 * TROW_B + ks * 32);
                ldsm_x4(bl[nfp], bB0 + TILE_B + nfp * 16 * TROW_B + ks * 32);
            }
#pragma unroll
            for (int nfp = 0; nfp < 4; ++nfp)
#pragma unroll
                for (int hf = 0; hf < 2; ++hf) {
                    const int nf = nfp * 2 + hf;
                    const uint32_t b0h = bh[nfp][hf * 2], b1h = bh[nfp][hf * 2 + 1];
                    const uint32_t b0l = bl[nfp][hf * 2], b1l = bl[nfp][hf * 2 + 1];
#pragma unroll
                    for (int mf = 0; mf < 2; ++mf) {
                        mma16816(acc[mf][nf], ah[mf][0], ah[mf][1], ah[mf][2], ah[mf][3], b0h, b1h);
                        mma16816(acc[mf][nf], al[mf][0], al[mf][1], al[mf][2], al[mf][3], b0h, b1h);
                        mma16816(acc[mf][nf], ah[mf][0], ah[mf][1], ah[mf][2], ah[mf][3], b0l, b1l);
                    }
                }
        }
        __syncthreads();
    }
#undef ISSUE
}

// ---------------------------------------------------------------------------
// GEMM-1 (HMMA): h = feat @ W^T; epilogue splits h + fused src/dst logits.
// ---------------------------------------------------------------------------
__global__ __launch_bounds__(256) void gemm1_tc_kernel(const float* __restrict__ wsrc,
                                                       const float* __restrict__ wdst) {
    extern __shared__ char sm[];
    const int m0 = blockIdx.y << 7;
    const int n0 = blockIdx.x << 7;
    float acc[2][8][4];
#pragma unroll
    for (int mf = 0; mf < 2; ++mf)
#pragma unroll
        for (int nf = 0; nf < 8; ++nf)
#pragma unroll
            for (int q = 0; q < 4; ++q) acc[mf][nf][q] = 0.f;

    hmma_mainloop(acc, g_fh, g_fl, g_w1h, g_w1l, m0, n0, sm);

    const int warp = threadIdx.x >> 5, lane = threadIdx.x & 31;
    const int wm = warp & 3, wn = warp >> 2;
    const int g = lane >> 2, t = lane & 3;
    const int head = (n0 >> 6) + wn;

    float sd[2][2], dd[2][2];
#pragma unroll
    for (int mf = 0; mf < 2; ++mf) sd[mf][0] = sd[mf][1] = dd[mf][0] = dd[mf][1] = 0.f;

#pragma unroll
    for (int mf = 0; mf < 2; ++mf) {
        const int m = m0 + wm * 32 + mf * 16 + g;
        const int b = m >> 9, i = m & (N_ - 1);
        const int ba = b * A_ + head;
#pragma unroll
        for (int nf = 0; nf < 8; ++nf) {
            const int e = nf * 8 + 2 * t;
            __nv_bfloat16 h0, l0, h1, l1;
            split2(acc[mf][nf][0], h0, l0);
            split2(acc[mf][nf][1], h1, l1);
            *(__nv_bfloat162*)&g_hbh[((size_t)(ba * N_ + i)) * E_ + e] = __nv_bfloat162(h0, h1);
            *(__nv_bfloat162*)&g_hbl[((size_t)(ba * N_ + i)) * E_ + e] = __nv_bfloat162(l0, l1);
            split2(acc[mf][nf][2], h0, l0);
            split2(acc[mf][nf][3], h1, l1);
            *(__nv_bfloat162*)&g_hbh[((size_t)(ba * N_ + i + 8)) * E_ + e] = __nv_bfloat162(h0, h1);
            *(__nv_bfloat162*)&g_hbl[((size_t)(ba * N_ + i + 8)) * E_ + e] = __nv_bfloat162(l0, l1);
            float2 ws = *(const float2*)(wsrc + head * E_ + e);
            float2 wd = *(const float2*)(wdst + head * E_ + e);
            float t0 = tanhf(acc[mf][nf][0]), t1 = tanhf(acc[mf][nf][1]);
            float t2 = tanhf(acc[mf][nf][2]), t3 = tanhf(acc[mf][nf][3]);
            sd[mf][0] += t0 * ws.x + t1 * ws.y;
            sd[mf][1] += t2 * ws.x + t3 * ws.y;
            dd[mf][0] += t0 * wd.x + t1 * wd.y;
            dd[mf][1] += t2 * wd.x + t3 * wd.y;
        }
#pragma unroll
        for (int rh = 0; rh < 2; ++rh) {
            float s = sd[mf][rh], d = dd[mf][rh];
            s += __shfl_xor_sync(0xffffffffu, s, 1);
            s += __shfl_xor_sync(0xffffffffu, s, 2);
            d += __shfl_xor_sync(0xffffffffu, d, 1);
            d += __shfl_xor_sync(0xffffffffu, d, 2);
            if (t == 0) {
                g_src[ba * N_ + i + rh * 8] = s;
                g_dst[ba * N_ + i + rh * 8] = d;
            }
        }
    }
}

// ---------------------------------------------------------------------------
// GEMM-2 (HMMA) + fused epilogue
// ---------------------------------------------------------------------------
__device__ __forceinline__ float blend_one(float accv, float hb, float att, float f) {
    float gt = 1.f / (1.f + __expf(-(accv + hb)));
    float fo = att > 0.f ? att : (__expf(att) - 1.f);
    return gt * fo + (1.f - gt) * f;
}

__global__ __launch_bounds__(256) void gemm2_tc_kernel(const float* __restrict__ feat,
                                                       const float* __restrict__ Hb,
                                                       float* __restrict__ out) {
    extern __shared__ char sm[];
    const int m0 = blockIdx.y << 7;
    const int n0 = blockIdx.x << 7;
    float acc[2][8][4];
#pragma unroll
    for (int mf = 0; mf < 2; ++mf)
#pragma unroll
        for (int nf = 0; nf < 8; ++nf)
#pragma unroll
            for (int q = 0; q < 4; ++q) acc[mf][nf][q] = 0.f;

    hmma_mainloop(acc, g_fh, g_fl, g_w2h, g_w2l, m0, n0, sm);

    const int warp = threadIdx.x >> 5, lane = threadIdx.x & 31;
    const int wm = warp & 3, wn = warp >> 2;
    const int g = lane >> 2, t = lane & 3;
#pragma unroll
    for (int mf = 0; mf < 2; ++mf)
#pragma unroll
        for (int nf = 0; nf < 8; ++nf) {
            const int m = m0 + wm * 32 + mf * 16 + g;
            const int n = n0 + wn * 64 + nf * 8 + 2 * t;
            float2 hb = *(const float2*)(Hb + n);
#pragma unroll
            for (int rr = 0; rr < 2; ++rr) {
                const int mm = m + rr * 8;
                float2 av = *(const float2*)(g_att + (size_t)mm * D_ + n);
                float2 fv = *(const float2*)(feat + (size_t)mm * D_ + n);
                float2 ov;
                ov.x = blend_one(acc[mf][nf][rr * 2 + 0], hb.x, av.x, fv.x);
                ov.y = blend_one(acc[mf][nf][rr * 2 + 1], hb.y, av.y, fv.y);
                *(float2*)(out + (size_t)mm * D_ + n) = ov;
            }
        }
}

// ---------------------------------------------------------------------------
// Attention (HMMA, unnormalized-softmax + streamed H chunks):
// Phase A: vectors; issue H chunk 0 (cp.async double buffer, 64 j-rows).
// Phase B: mask-bit packing only (no exp/max/sum).
// Phase C: per 64-j chunk: P = exp(leaky(src+dst)) masked (unnormalized),
//          row-sum accumulated in registers; HMMA Ph@Hh + Pl@Hh + Ph@Hl.
// Epilogue: out = acc / rowsum + bias.
// ---------------------------------------------------------------------------
#define HC_ROWB 144
#define HC_BUF_B (64 * HC_ROWB)          // 9216
#define P_ROWB 144
#define OFF_HCH 0                        // [2][64][144] hi        18432
#define OFF_HCL 18432                    // [2][64][144] lo        18432
#define OFF_PBH 36864                    // [128][144]             18432
#define OFF_PBL 55296                    //                        18432
#define OFF_SRC 73728                    // 128 f32 (512B)
#define OFF_DST 74240                    // 512 f32 (2048B)
#define OFF_MS  76288                    // 32x128 u16 (8192B)
#define OFF_SUM 84480                    // 128 f32 (512B)
#define ATT_SMEM_B 84992

__global__ __launch_bounds__(256, 2) void attn_kernel(const void* __restrict__ adjv,
                                                      const float* __restrict__ bbias) {
    extern __shared__ char sm[];
    const uint32_t smu = smem_u32(sm);
    char* Pbh = sm + OFF_PBH;
    char* Pbl = sm + OFF_PBL;
    float* s_src = (float*)(sm + OFF_SRC);
    float* s_dst = (float*)(sm + OFF_DST);
    float* s_sum = (float*)(sm + OFF_SUM);
    unsigned short* Ms = (unsigned short*)(sm + OFF_MS);   // [32 jwords][128 rows]

    const int tid = threadIdx.x;
    const int lane = tid & 31, warp = tid >> 5;
    const int b = blockIdx.z, a = blockIdx.y, it = blockIdx.x;
    const int ba = b * A_ + a;
    const int i0 = it * 128;

    const __nv_bfloat16* srcH = g_hbh + (size_t)ba * N_ * E_;
    const __nv_bfloat16* srcL = g_hbl + (size_t)ba * N_ * E_;

#define ISSUE_H(jc, buf) do {                                                \
    const int _j0 = (jc) * 64;                                               \
    _Pragma("unroll")                                                        \
    for (int _c = 0; _c < 2; ++_c) {                                         \
        const int _idx = tid * 2 + _c;                                       \
        const int _jr = _idx >> 3, _q = _idx & 7;                            \
        const uint32_t _dst = smu + OFF_HCH + (buf) * HC_BUF_B + _jr * HC_ROWB + _q * 16; \
        CP16(_dst, srcH + (size_t)(_j0 + _jr) * E_ + _q * 8);                \
        CP16(_dst + (OFF_HCL - OFF_HCH), srcL + (size_t)(_j0 + _jr) * E_ + _q * 8); \
    }                                                                        \
    CP_COMMIT(); } while (0)

    // ---- Phase A: issue chunk 0; load vectors ----
    ISSUE_H(0, 0);
    if (tid < 128) s_src[tid] = g_src[ba * N_ + i0 + tid];
    s_dst[tid] = g_dst[ba * N_ + tid];
    s_dst[tid + 256] = g_dst[ba * N_ + tid + 256];
    __syncthreads();   // s_dst visible for Phase B

    // ---- Phase B: mask-bit packing only ----
    const int adj_int = g_adj_int;
    for (int rr = warp; rr < 128; rr += 8) {
        const size_t rowoff = (size_t)(b * N_ + i0 + rr) * N_;
        unsigned mbits = 0;
        if (adj_int) {
            const uint4* ap = (const uint4*)((const int*)adjv + rowoff + lane * 16);
#pragma unroll
            for (int q = 0; q < 4; ++q) {
                uint4 w = ap[q];
                mbits |= (w.x ? 1u : 0u) << (q * 4 + 0);
                mbits |= (w.y ? 1u : 0u) << (q * 4 + 1);
                mbits |= (w.z ? 1u : 0u) << (q * 4 + 2);
                mbits |= (w.w ? 1u : 0u) << (q * 4 + 3);
            }
        } else {
            uint4 w = *(const uint4*)((const uint8_t*)adjv + rowoff + lane * 16);
            unsigned ws[4] = {w.x, w.y, w.z, w.w};
#pragma unroll
            for (int q = 0; q < 4; ++q)
#pragma unroll
                for (int bq = 0; bq < 4; ++bq)
                    mbits |= (((ws[q] >> (8 * bq)) & 0xffu) ? 1u : 0u) << (q * 4 + bq);
        }
        Ms[lane * 128 + rr] = (unsigned short)mbits;
    }
    __syncthreads();   // Ms visible

    // ---- Phase C ----
    const int wm = warp & 3, wn = warp >> 2;
    const int r = tid >> 1, jseg = (tid & 1) * 32;
    const float srcv = s_src[r];

    const int arow = (lane & 7) + ((lane >> 3) & 1) * 8;
    const int acolb = (lane >> 4) * 16;
    const uint32_t aP0 = smu + OFF_PBH + (uint32_t)(wm * 32 + arow) * P_ROWB + acolb;
    const int jrow = lane & 15;
    const int ecolb = (lane >> 4) * 16;
    const uint32_t bH0 = smu + OFF_HCH + (uint32_t)jrow * HC_ROWB + (wn * 32) * 2 + ecolb;

    float acc[2][4][4];
#pragma unroll
    for (int mf = 0; mf < 2; ++mf)
#pragma unroll
        for (int nf = 0; nf < 4; ++nf)
#pragma unroll
            for (int q = 0; q < 4; ++q) acc[mf][nf][q] = 0.f;

    float psum = 0.f;

    for (int jc = 0; jc < 8; ++jc) {
        const int j0 = jc * 64;
        // P chunk gen (unnormalized exp; accumulate row sum)
        {
            const int jb = j0 + jseg;
            uint32_t mw0 = Ms[(jb >> 4) * 128 + r];
            uint32_t mw1 = Ms[((jb >> 4) + 1) * 128 + r];
            uint32_t mbits = mw0 | (mw1 << 16);
#pragma unroll
            for (int q = 0; q < 32; q += 4) {
                float4 dv = *(const float4*)&s_dst[jb + q];
                float p[4];
#pragma unroll
                for (int e = 0; e < 4; ++e) {
                    float v = srcv + (&dv.x)[e];
                    v = v >= 0.f ? v : 0.2f * v;
                    p[e] = ((mbits >> (q + e)) & 1u) ? __expf(v) : 0.f;
                    psum += p[e];
                }
                __nv_bfloat16 h0, l0, h1, l1;
                split2(p[0], h0, l0); split2(p[1], h1, l1);
                *(__nv_bfloat162*)(Pbh + r * P_ROWB + (jseg + q) * 2) = __nv_bfloat162(h0, h1);
                *(__nv_bfloat162*)(Pbl + r * P_ROWB + (jseg + q) * 2) = __nv_bfloat162(l0, l1);
                split2(p[2], h0, l0); split2(p[3], h1, l1);
                *(__nv_bfloat162*)(Pbh + r * P_ROWB + (jseg + q + 2) * 2) = __nv_bfloat162(h0, h1);
                *(__nv_bfloat162*)(Pbl + r * P_ROWB + (jseg + q + 2) * 2) = __nv_bfloat162(l0, l1);
            }
        }
        if (jc + 1 < 8) { ISSUE_H(jc + 1, (jc + 1) & 1); CP_WAIT1(); }
        else            { CP_WAIT0(); }
        __syncthreads();   // P visible + H chunk ready

        const uint32_t bbuf = bH0 + (jc & 1) * HC_BUF_B;
#pragma unroll
        for (int ks = 0; ks < 4; ++ks) {
            uint32_t ah[2][4], al[2][4], bh[2][4], bl[2][4];
#pragma unroll
            for (int mf = 0; mf < 2; ++mf) {
                ldsm_x4(ah[mf], aP0 + mf * 16 * P_ROWB + ks * 32);
                ldsm_x4(al[mf], aP0 + (OFF_PBL - OFF_PBH) + mf * 16 * P_ROWB + ks * 32);
            }
            const uint32_t bbase = bbuf + (uint32_t)(ks * 16) * HC_ROWB;
#pragma unroll
            for (int nfp = 0; nfp < 2; ++nfp) {
                ldsm_x4_t(bh[nfp], bbase + nfp * 32);
                ldsm_x4_t(bl[nfp], bbase + (OFF_HCL - OFF_HCH) + nfp * 32);
            }
#pragma unroll
            for (int nfp = 0; nfp < 2; ++nfp)
#pragma unroll
                for (int hf = 0; hf < 2; ++hf) {
                    const int nf = nfp * 2 + hf;
                    const uint32_t b0h = bh[nfp][hf * 2], b1h = bh[nfp][hf * 2 + 1];
                    const uint32_t b0l = bl[nfp][hf * 2], b1l = bl[nfp][hf * 2 + 1];
#pragma unroll
                    for (int mf = 0; mf < 2; ++mf) {
                        mma16816(acc[mf][nf], ah[mf][0], ah[mf][1], ah[mf][2], ah[mf][3], b0h, b1h);
                        mma16816(acc[mf][nf], al[mf][0], al[mf][1], al[mf][2], al[mf][3], b0h, b1h);
                        mma16816(acc[mf][nf], ah[mf][0], ah[mf][1], ah[mf][2], ah[mf][3], b0l, b1l);
                    }
                }
        }
        __syncthreads();   // done reading P (and H buf) before next-iter writes
    }
#undef ISSUE_H

    // row-sum: pair-reduce and publish
    psum += __shfl_xor_sync(0xffffffffu, psum, 1);
    if ((tid & 1) == 0) s_sum[r] = psum;
    __syncthreads();

    // ---- epilogue: normalize + bias + store ----
    const int g = lane >> 2, t = lane & 3;
#pragma unroll
    for (int mf = 0; mf < 2; ++mf) {
        const int rl = wm * 32 + mf * 16 + g;
        const float inv0 = __fdividef(1.f, s_sum[rl]);
        const float inv1 = __fdividef(1.f, s_sum[rl + 8]);
#pragma unroll
        for (int nf = 0; nf < 4; ++nf) {
            const int row = i0 + rl;
            const int col = wn * 32 + nf * 8 + 2 * t;
            float2 bias = *(const float2*)(bbias + col);
            float2 v0 = make_float2(fmaf(acc[mf][nf][0], inv0, bias.x),
                                    fmaf(acc[mf][nf][1], inv0, bias.y));
            float2 v1 = make_float2(fmaf(acc[mf][nf][2], inv1, bias.x),
                                    fmaf(acc[mf][nf][3], inv1, bias.y));
            *(float2*)&g_att[(size_t)(b * N_ + row) * D_ + a * E_ + col] = v0;
            *(float2*)&g_att[(size_t)(b * N_ + row + 8) * D_ + a * E_ + col] = v1;
        }
    }
}

// ---------------------------------------------------------------------------
extern "C" void kernel_launch(void* const* d_in, const int* in_sizes, int n_in,
                              void* d_out, int out_size) {
    const float* feat = (const float*)d_in[0];
    const void* adj = d_in[1];
    const float* W = (const float*)d_in[2];
    const float* bbias = (const float*)d_in[3];
    const float* wsrc = (const float*)d_in[4];
    const float* wdst = (const float*)d_in[5];
    const float* Hw = (const float*)d_in[6];
    const float* Hb = (const float*)d_in[7];
    float* out = (float*)d_out;

    detect_adj_kernel<<<1, 32>>>((const int*)adj);
    conv_feat_kernel<<<M_ * D_ / 1024, 256>>>(feat);
    conv_w1_kernel<<<dim3(A_, D_ / 64), 256>>>(W);
    conv_w2_kernel<<<D_ * D_ / 1024, 256>>>(Hw);

    cudaFuncSetAttribute(gemm1_tc_kernel, cudaFuncAttributeMaxDynamicSharedMemorySize, GEMM_SMEM);
    cudaFuncSetAttribute(gemm2_tc_kernel, cudaFuncAttributeMaxDynamicSharedMemorySize, GEMM_SMEM);
    cudaFuncSetAttribute(attn_kernel, cudaFuncAttributeMaxDynamicSharedMemorySize, ATT_SMEM_B);

    gemm1_tc_kernel<<<dim3(D_ / 128, M_ / 128), 256, GEMM_SMEM>>>(wsrc, wdst);

    attn_kernel<<<dim3(N_ / 128, A_, B_), 256, ATT_SMEM_B>>>(adj, bbias);

    gemm2_tc_kernel<<<dim3(D_ / 128, M_ / 128), 256, GEMM_SMEM>>>(feat, Hb, out);
}